// round 5
// baseline (speedup 1.0000x reference)
#include <cuda_runtime.h>
#include <cuda_bf16.h>
#include <cstdint>

// Problem constants (fixed shapes per reference)
#define NN        500000   // minibatch nodes
#define D_IN      256
#define EMBED     128
#define TM        128      // nodes per GEMM block
#define TK        32
#define GEMM_THREADS 256

// ---------------------------------------------------------------------------
// Scratch (no cudaMalloc allowed): compacted type-0 node list
// ---------------------------------------------------------------------------
__device__ int g_count;
__device__ int g_is64;       // 1 if index arrays are int64, 0 if int32
__device__ int g_rows[NN];   // original minibatch row index
__device__ int g_feat[NN];   // feat0 row index (type_ids)

// ---------------------------------------------------------------------------
// f32x2 helpers (sm_100+ packed fp32)
// ---------------------------------------------------------------------------
__device__ __forceinline__ unsigned long long pk2(float lo, float hi) {
    unsigned long long r;
    asm("mov.b64 %0, {%1, %2};" : "=l"(r) : "f"(lo), "f"(hi));
    return r;
}
__device__ __forceinline__ void fma2(unsigned long long& acc,
                                     unsigned long long a,
                                     unsigned long long b) {
    asm("fma.rn.f32x2 %0, %1, %2, %0;" : "+l"(acc) : "l"(a), "l"(b));
}

// Dtype-agnostic index read
__device__ __forceinline__ int read_idx(const void* p, int i, int is64) {
    if (is64) return (int)((const long long*)p)[i];
    return ((const int*)p)[i];
}

// ---------------------------------------------------------------------------
// Kernel 0: reset counter + detect index dtype.
// If node_ids is really int64 (values < 2^31, nonneg), every odd int32 word
// of the first 64 elements is 0. For genuine int32 data (uniform in [0,1e6))
// that is essentially impossible. Deterministic for fixed inputs.
// ---------------------------------------------------------------------------
__global__ void k_reset_detect(const int* node_ids_as_i32) {
    bool odd_all_zero = true;
    for (int j = threadIdx.x; j < 64; j += 32)
        if (node_ids_as_i32[2 * j + 1] != 0) odd_all_zero = false;
    const unsigned b = __ballot_sync(0xffffffffu, odd_all_zero);
    if (threadIdx.x == 0) {
        g_is64  = (b == 0xffffffffu) ? 1 : 0;
        g_count = 0;
    }
}

// ---------------------------------------------------------------------------
// Kernel 1: warp-aggregated compaction of type-0 nodes + fused embedding copy
// for type-1 nodes (warp-per-node float4 copy, fully coalesced).
// ---------------------------------------------------------------------------
__global__ void k_compact_embed(const void* __restrict__ node_ids,
                                const void* __restrict__ node_tids,
                                const void* __restrict__ type_ids,
                                const float* __restrict__ embed_table,
                                float* __restrict__ out) {
    const int is64    = g_is64;
    const int lane    = threadIdx.x & 31;
    const int warpId  = (blockIdx.x * blockDim.x + threadIdx.x) >> 5;
    const int nWarps  = (gridDim.x * blockDim.x) >> 5;
    const int nChunks = (NN + 31) >> 5;

    for (int chunk = warpId; chunk < nChunks; chunk += nWarps) {
        const int base = chunk << 5;
        const int i    = base + lane;
        const bool valid = (i < NN);

        int tid_i = -1;
        int my_nid = 0, my_feat = 0;
        if (valid) {
            tid_i   = read_idx(node_tids, i, is64);
            my_nid  = read_idx(node_ids,  i, is64);
            my_feat = read_idx(type_ids,  i, is64);
        }

        // --- compaction of type-0 nodes ---
        const unsigned mask0 = __ballot_sync(0xffffffffu, valid && tid_i == 0);
        const int cnt = __popc(mask0);
        int posBase = 0;
        if (lane == 0 && cnt > 0) posBase = atomicAdd(&g_count, cnt);
        posBase = __shfl_sync(0xffffffffu, posBase, 0);
        if (valid && tid_i == 0) {
            const int rank = __popc(mask0 & ((1u << lane) - 1u));
            g_rows[posBase + rank] = i;
            g_feat[posBase + rank] = my_feat;
        }

        // --- embedding copy for type-1 nodes: one warp copies one 512B row ---
        unsigned mask1 = __ballot_sync(0xffffffffu, valid && tid_i == 1);
        while (mask1) {
            const int j = __ffs(mask1) - 1;
            mask1 &= mask1 - 1;
            const int nid = __shfl_sync(0xffffffffu, my_nid, j);
            const float4* src = reinterpret_cast<const float4*>(
                embed_table + (size_t)nid * EMBED);
            float4* dst = reinterpret_cast<float4*>(
                out + (size_t)(base + j) * EMBED);
            dst[lane] = src[lane];   // 32 lanes x float4 = 128 floats
        }
    }
}

// ---------------------------------------------------------------------------
// Kernel 2: gathered GEMM over compacted rows.
//   [rows, 256] (gathered from feat0) @ W0[256,128] -> scatter to out.
// Block: 128 nodes x 128 cols; thread: 8 rows x 8 cols, rows packed in pairs
// for fma.rn.f32x2 (2x FP32 throughput).
// ---------------------------------------------------------------------------
__global__ void __launch_bounds__(GEMM_THREADS, 2)
k_gemm(const float* __restrict__ feat0,
       const float* __restrict__ W0,
       float* __restrict__ out) {
    __shared__ float Xs[TK][TM + 4];   // stride 132 keeps LDS.128 16B-aligned
    __shared__ float Ws[TK][EMBED];
    __shared__ int   srow[TM];
    __shared__ int   sfeat[TM];

    const int count = g_count;
    const int m0 = blockIdx.x * TM;
    if (m0 >= count) return;
    const int rows = min(TM, count - m0);

    const int tid = threadIdx.x;
    const int tx = tid & 15;    // output-col group (8 cols)
    const int ty = tid >> 4;    // output-row group (8 rows)

    // tile row metadata
    if (tid < TM) {
        const bool v = tid < rows;
        srow[tid]  = v ? g_rows[m0 + tid] : 0;
        sfeat[tid] = v ? g_feat[m0 + tid] : 0;
    }
    __syncthreads();

    unsigned long long acc2[4][8];
#pragma unroll
    for (int p = 0; p < 4; ++p)
#pragma unroll
        for (int c = 0; c < 8; ++c) acc2[p][c] = 0ull;

    // X-tile load assignment: thread t loads half-row (16 floats) of row t>>1
    const int xr = tid >> 1;
    const int xh = tid & 1;
    const float* xsrc_row = feat0 + (size_t)sfeat[xr] * D_IN + xh * 16;

    for (int k0 = 0; k0 < D_IN; k0 += TK) {
        // --- load X tile (gathered, transposed into Xs[k][row]) ---
        const float4* xsrc = reinterpret_cast<const float4*>(xsrc_row + k0);
#pragma unroll
        for (int j = 0; j < 4; ++j) {
            const float4 v = xsrc[j];
            const int kk = xh * 16 + j * 4;
            Xs[kk + 0][xr] = v.x;
            Xs[kk + 1][xr] = v.y;
            Xs[kk + 2][xr] = v.z;
            Xs[kk + 3][xr] = v.w;
        }
        // --- load W tile (row-major copy, coalesced) ---
        const float4* wsrc = reinterpret_cast<const float4*>(W0);
#pragma unroll
        for (int j = 0; j < 4; ++j) {
            const int lin = tid + j * GEMM_THREADS;      // float4 index, 0..1023
            const int kk  = lin >> 5;                    // 32 float4 per row
            const int c4  = lin & 31;
            reinterpret_cast<float4*>(&Ws[kk][0])[c4] =
                wsrc[(size_t)(k0 + kk) * (EMBED / 4) + c4];
        }
        __syncthreads();

#pragma unroll 8
        for (int kk = 0; kk < TK; ++kk) {
            const float4 a0 = *reinterpret_cast<const float4*>(&Xs[kk][ty * 8]);
            const float4 a1 = *reinterpret_cast<const float4*>(&Xs[kk][ty * 8 + 4]);
            unsigned long long x2[4];
            x2[0] = pk2(a0.x, a0.y);
            x2[1] = pk2(a0.z, a0.w);
            x2[2] = pk2(a1.x, a1.y);
            x2[3] = pk2(a1.z, a1.w);

            const float4 b0 = *reinterpret_cast<const float4*>(&Ws[kk][tx * 8]);
            const float4 b1 = *reinterpret_cast<const float4*>(&Ws[kk][tx * 8 + 4]);
            const float bs[8] = {b0.x, b0.y, b0.z, b0.w, b1.x, b1.y, b1.z, b1.w};
#pragma unroll
            for (int c = 0; c < 8; ++c) {
                const unsigned long long bb = pk2(bs[c], bs[c]);
#pragma unroll
                for (int p = 0; p < 4; ++p) fma2(acc2[p][c], x2[p], bb);
            }
        }
        __syncthreads();
    }

    // --- epilogue: unpack row-pairs, scatter float4s to out ---
#pragma unroll
    for (int p = 0; p < 4; ++p) {
#pragma unroll
        for (int rr = 0; rr < 2; ++rr) {
            const int rloc = ty * 8 + 2 * p + rr;
            if (rloc < rows) {
                union { unsigned long long u; float f[2]; } cv;
                float4 v0, v1;
                cv.u = acc2[p][0]; v0.x = cv.f[rr];
                cv.u = acc2[p][1]; v0.y = cv.f[rr];
                cv.u = acc2[p][2]; v0.z = cv.f[rr];
                cv.u = acc2[p][3]; v0.w = cv.f[rr];
                cv.u = acc2[p][4]; v1.x = cv.f[rr];
                cv.u = acc2[p][5]; v1.y = cv.f[rr];
                cv.u = acc2[p][6]; v1.z = cv.f[rr];
                cv.u = acc2[p][7]; v1.w = cv.f[rr];
                float* dst = out + (size_t)srow[rloc] * EMBED + tx * 8;
                reinterpret_cast<float4*>(dst)[0] = v0;
                reinterpret_cast<float4*>(dst)[1] = v1;
            }
        }
    }
}

// ---------------------------------------------------------------------------
// Launch
// ---------------------------------------------------------------------------
extern "C" void kernel_launch(void* const* d_in, const int* in_sizes, int n_in,
                              void* d_out, int out_size) {
    const void*  node_ids   = d_in[0];
    const void*  node_tids  = d_in[1];
    const void*  type_ids   = d_in[2];
    const float* feat0      = (const float*)d_in[3];
    const float* W0         = (const float*)d_in[4];
    const float* embed_tab  = (const float*)d_in[5];
    float*       out        = (float*)d_out;

    k_reset_detect<<<1, 32>>>((const int*)node_ids);
    k_compact_embed<<<512, 256>>>(node_ids, node_tids, type_ids, embed_tab, out);
    const int gemmBlocks = (NN + TM - 1) / TM;   // worst case: all type-0
    k_gemm<<<gemmBlocks, GEMM_THREADS>>>(feat0, W0, out);
}

// round 9
// speedup vs baseline: 1.1474x; 1.1474x over previous
#include <cuda_runtime.h>
#include <cuda_bf16.h>
#include <cstdint>

// ---------------------------------------------------------------------------
// Problem constants
// ---------------------------------------------------------------------------
#define NN     500000
#define D_IN   256
#define EMBED  128
#define TM     128        // rows per GEMM tile
#define KC     128        // K elems per A chunk (2 chunks)
#define GT     256        // GEMM block threads

// SMEM layout (bytes), all 16B-aligned.
// B: [n][k] bf16, full K=256, row stride 528B (512 + 16 pad -> stride%128B = 16,
//    i.e. 4 banks mod 32 -> ldmatrix conflict-free across 8-row groups).
// A: [r][k] bf16 per 128-K chunk, row stride 272B (256 + 16 pad), same property.
#define SB_STRIDE  528
#define SA_STRIDE  272
#define SM_B_HI    0
#define SM_B_LO    67584        // 128*528
#define SM_A_HI    135168
#define SM_A_LO    169984       // +128*272
#define SM_SROW    204800
#define SM_SFEAT   205312
#define SMEM_TOTAL 205824

// ---------------------------------------------------------------------------
// Device scratch (no cudaMalloc allowed)
// ---------------------------------------------------------------------------
__device__ int g_count;
__device__ int g_is64;
__device__ int g_rows[NN];
__device__ int g_feat[NN];
__device__ __align__(16) __nv_bfloat16 g_W0T_hi[EMBED * D_IN];  // [n][k]
__device__ __align__(16) __nv_bfloat16 g_W0T_lo[EMBED * D_IN];

// ---------------------------------------------------------------------------
// PTX helpers (base sm_103 ISA only: ldmatrix + mma.sync)
// ---------------------------------------------------------------------------
__device__ __forceinline__ uint32_t smem_u32(const void* p) {
    uint32_t a;
    asm("{ .reg .u64 t; cvta.to.shared.u64 t, %1; cvt.u32.u64 %0, t; }"
        : "=r"(a) : "l"(p));
    return a;
}
__device__ __forceinline__ void ldsm_x4(uint32_t* r, uint32_t addr) {
    asm volatile("ldmatrix.sync.aligned.m8n8.x4.shared.b16 {%0,%1,%2,%3}, [%4];"
                 : "=r"(r[0]), "=r"(r[1]), "=r"(r[2]), "=r"(r[3]) : "r"(addr));
}
__device__ __forceinline__ void mma_bf16(float* d, const uint32_t* a,
                                         const uint32_t* b) {
    asm volatile(
        "mma.sync.aligned.m16n8k16.row.col.f32.bf16.bf16.f32 "
        "{%0,%1,%2,%3}, {%4,%5,%6,%7}, {%8,%9}, {%0,%1,%2,%3};"
        : "+f"(d[0]), "+f"(d[1]), "+f"(d[2]), "+f"(d[3])
        : "r"(a[0]), "r"(a[1]), "r"(a[2]), "r"(a[3]), "r"(b[0]), "r"(b[1]));
}

// Dtype-agnostic index read
__device__ __forceinline__ int read_idx(const void* p, int i, int is64) {
    if (is64) return (int)((const long long*)p)[i];
    return ((const int*)p)[i];
}

// Split 8 floats into bf16 hi/lo and store as one uint4 each.
__device__ __forceinline__ void split8_store(char* smem, uint32_t off_hi,
                                             const float* f) {
    uint32_t hw[4], lw[4];
#pragma unroll
    for (int q = 0; q < 4; ++q) {
        const float a = f[2 * q], b = f[2 * q + 1];
        const __nv_bfloat16 ah = __float2bfloat16_rn(a);
        const __nv_bfloat16 bh = __float2bfloat16_rn(b);
        const __nv_bfloat16 al = __float2bfloat16_rn(a - __bfloat162float(ah));
        const __nv_bfloat16 bl = __float2bfloat16_rn(b - __bfloat162float(bh));
        hw[q] = (uint32_t)__bfloat16_as_ushort(ah) |
                ((uint32_t)__bfloat16_as_ushort(bh) << 16);
        lw[q] = (uint32_t)__bfloat16_as_ushort(al) |
                ((uint32_t)__bfloat16_as_ushort(bl) << 16);
    }
    *reinterpret_cast<uint4*>(smem + off_hi) = make_uint4(hw[0], hw[1], hw[2], hw[3]);
    *reinterpret_cast<uint4*>(smem + off_hi + (SM_A_LO - SM_A_HI)) =
        make_uint4(lw[0], lw[1], lw[2], lw[3]);
}

// Convert + store one 128xKC A chunk (thread t: row t>>1, K-half t&1 = 64 floats)
__device__ __forceinline__ void store_A_chunk(char* smem, int tid, const float4* v) {
    const int r = tid >> 1, h = tid & 1;
#pragma unroll
    for (int j = 0; j < 8; ++j) {
        const float f[8] = {v[2*j].x,   v[2*j].y,   v[2*j].z,   v[2*j].w,
                            v[2*j+1].x, v[2*j+1].y, v[2*j+1].z, v[2*j+1].w};
        split8_store(smem, (uint32_t)(SM_A_HI + r * SA_STRIDE + h * 128 + j * 16), f);
    }
}

// ---------------------------------------------------------------------------
// Kernel 0: reset counter + dtype detect + W0^T hi/lo prep (fused)
// ---------------------------------------------------------------------------
__global__ void k_prep(const float* __restrict__ W0, const int* node_ids_as_i32) {
    if (blockIdx.x == 0 && threadIdx.x < 32) {
        bool odd_zero = true;
        for (int j = threadIdx.x; j < 64; j += 32)
            if (node_ids_as_i32[2 * j + 1] != 0) odd_zero = false;
        const unsigned b = __ballot_sync(0xffffffffu, odd_zero);
        if (threadIdx.x == 0) {
            g_is64  = (b == 0xffffffffu) ? 1 : 0;
            g_count = 0;
        }
    }
    const int idx = blockIdx.x * blockDim.x + threadIdx.x;  // 0..32767
    const int n = idx >> 8, k = idx & 255;
    const float x = W0[k * EMBED + n];
    const __nv_bfloat16 hi = __float2bfloat16_rn(x);
    const __nv_bfloat16 lo = __float2bfloat16_rn(x - __bfloat162float(hi));
    g_W0T_hi[n * D_IN + k] = hi;
    g_W0T_lo[n * D_IN + k] = lo;
}

// ---------------------------------------------------------------------------
// Kernel 1: warp-aggregated compaction of type-0 nodes + fused embedding copy
// ---------------------------------------------------------------------------
__global__ void k_compact_embed(const void* __restrict__ node_ids,
                                const void* __restrict__ node_tids,
                                const void* __restrict__ type_ids,
                                const float* __restrict__ embed_table,
                                float* __restrict__ out) {
    const int is64    = g_is64;
    const int lane    = threadIdx.x & 31;
    const int warpId  = (blockIdx.x * blockDim.x + threadIdx.x) >> 5;
    const int nWarps  = (gridDim.x * blockDim.x) >> 5;
    const int nChunks = (NN + 31) >> 5;

    for (int chunk = warpId; chunk < nChunks; chunk += nWarps) {
        const int base = chunk << 5;
        const int i    = base + lane;
        const bool valid = (i < NN);

        int tid_i = -1, my_nid = 0, my_feat = 0;
        if (valid) {
            tid_i   = read_idx(node_tids, i, is64);
            my_nid  = read_idx(node_ids,  i, is64);
            my_feat = read_idx(type_ids,  i, is64);
        }

        const unsigned mask0 = __ballot_sync(0xffffffffu, valid && tid_i == 0);
        const int cnt = __popc(mask0);
        int posBase = 0;
        if (lane == 0 && cnt > 0) posBase = atomicAdd(&g_count, cnt);
        posBase = __shfl_sync(0xffffffffu, posBase, 0);
        if (valid && tid_i == 0) {
            const int rank = __popc(mask0 & ((1u << lane) - 1u));
            g_rows[posBase + rank] = i;
            g_feat[posBase + rank] = my_feat;
        }

        unsigned mask1 = __ballot_sync(0xffffffffu, valid && tid_i == 1);
        while (mask1) {
            const int j = __ffs(mask1) - 1;
            mask1 &= mask1 - 1;
            const int nid = __shfl_sync(0xffffffffu, my_nid, j);
            const float4* src = reinterpret_cast<const float4*>(
                embed_table + (size_t)nid * EMBED);
            float4* dst = reinterpret_cast<float4*>(
                out + (size_t)(base + j) * EMBED);
            dst[lane] = src[lane];
        }
    }
}

// ---------------------------------------------------------------------------
// Kernel 2: HMMA split-bf16 gathered GEMM.
// D[128,128] = sum over K of (Ahi+Alo)(Bhi+Blo), dropping lo*lo (~4e-6 rel).
// 8 warps; warp w: rows (w&3)*32..+31, cols (w>>2)*64..+63.
// ---------------------------------------------------------------------------
__global__ void __launch_bounds__(GT)
k_gemm_mma(const float* __restrict__ feat0, float* __restrict__ out) {
    extern __shared__ __align__(16) char smem[];

    const int count = g_count;
    const int m0 = blockIdx.x * TM;
    if (m0 >= count) return;
    const int rows = min(TM, count - m0);

    const int tid  = threadIdx.x;
    const int w    = tid >> 5;
    const int lane = tid & 31;
    const int mw   = (w & 3) * 32;
    const int nw   = (w >> 2) * 64;
    const uint32_t sb = smem_u32(smem);

    int* srow  = reinterpret_cast<int*>(smem + SM_SROW);
    int* sfeat = reinterpret_cast<int*>(smem + SM_SFEAT);
    if (tid < TM) {
        const bool v = tid < rows;
        srow[tid]  = v ? g_rows[m0 + tid] : 0;
        sfeat[tid] = v ? g_feat[m0 + tid] : g_feat[m0];
    }

    // --- stage B (W0^T hi/lo, full K) into padded SMEM ---
    {
        const int n = tid >> 1, h = tid & 1;
        const uint4* srcH = reinterpret_cast<const uint4*>(g_W0T_hi + n * D_IN + h * 128);
        const uint4* srcL = reinterpret_cast<const uint4*>(g_W0T_lo + n * D_IN + h * 128);
        char* dstH = smem + SM_B_HI + n * SB_STRIDE + h * 256;
        char* dstL = smem + SM_B_LO + n * SB_STRIDE + h * 256;
#pragma unroll
        for (int j = 0; j < 16; ++j) {
            *reinterpret_cast<uint4*>(dstH + j * 16) = srcH[j];
            *reinterpret_cast<uint4*>(dstL + j * 16) = srcL[j];
        }
    }
    __syncthreads();

    // --- gather + convert A chunk 0 ---
    const int ar = tid >> 1, ah = tid & 1;
    const float4* arow = reinterpret_cast<const float4*>(
        feat0 + (size_t)sfeat[ar] * D_IN) + ah * 16;

    float4 v[16];
#pragma unroll
    for (int j = 0; j < 16; ++j) v[j] = arow[j];
    store_A_chunk(smem, tid, v);
    __syncthreads();

    // prefetch chunk 1 (overlaps chunk-0 MMA; 1 block/SM -> regs are free)
#pragma unroll
    for (int j = 0; j < 16; ++j) v[j] = arow[32 + j];

    float acc[2][8][4];
#pragma unroll
    for (int mf = 0; mf < 2; ++mf)
#pragma unroll
        for (int nf = 0; nf < 8; ++nf)
#pragma unroll
            for (int q = 0; q < 4; ++q) acc[mf][nf][q] = 0.0f;

    // ldmatrix lane address components (constant across ksteps)
    const uint32_t a_row  = (uint32_t)(mw + (lane & 15));
    const uint32_t a_coff = (uint32_t)((lane >> 4) * 16);
    const uint32_t b_row  = (uint32_t)(nw + (lane >> 4) * 8 + (lane & 7));
    const uint32_t b_coff = (uint32_t)(((lane >> 3) & 1) * 16);

    for (int chunk = 0; chunk < 2; ++chunk) {
#pragma unroll
        for (int kk = 0; kk < KC / 16; ++kk) {
            const uint32_t kbA = (uint32_t)(kk * 32) + a_coff;
            const uint32_t kbB = (uint32_t)(chunk * 256 + kk * 32) + b_coff;

            uint32_t ahi[2][4], alo[2][4];
#pragma unroll
            for (int mf = 0; mf < 2; ++mf) {
                const uint32_t addr =
                    sb + SM_A_HI + (a_row + mf * 16) * SA_STRIDE + kbA;
                ldsm_x4(ahi[mf], addr);
                ldsm_x4(alo[mf], addr + (SM_A_LO - SM_A_HI));
            }
            uint32_t bhi[8][2], blo[8][2];
#pragma unroll
            for (int np = 0; np < 4; ++np) {
                const uint32_t addr =
                    sb + SM_B_HI + (b_row + np * 16) * SB_STRIDE + kbB;
                uint32_t t[4];
                ldsm_x4(t, addr);
                bhi[np*2][0] = t[0]; bhi[np*2][1] = t[1];
                bhi[np*2+1][0] = t[2]; bhi[np*2+1][1] = t[3];
                ldsm_x4(t, addr + (SM_B_LO - SM_B_HI));
                blo[np*2][0] = t[0]; blo[np*2][1] = t[1];
                blo[np*2+1][0] = t[2]; blo[np*2+1][1] = t[3];
            }
#pragma unroll
            for (int mf = 0; mf < 2; ++mf)
#pragma unroll
                for (int nf = 0; nf < 8; ++nf) {
                    mma_bf16(acc[mf][nf], ahi[mf], bhi[nf]);
                    mma_bf16(acc[mf][nf], ahi[mf], blo[nf]);
                    mma_bf16(acc[mf][nf], alo[mf], bhi[nf]);
                }
        }
        if (chunk == 0) {
            __syncthreads();              // all ldmatrix of chunk 0 done
            store_A_chunk(smem, tid, v);  // overwrite A with chunk 1
            __syncthreads();
        }
    }

    // --- epilogue: scatter accumulators to out ---
    const int cr0 = lane >> 2;            // fragment row 0..7
    const int cc  = (lane & 3) * 2;       // fragment col (2 floats)
#pragma unroll
    for (int mf = 0; mf < 2; ++mf)
#pragma unroll
        for (int half = 0; half < 2; ++half) {
            const int rloc = mw + mf * 16 + cr0 + half * 8;
            if (rloc < rows) {
                float* dst = out + (size_t)srow[rloc] * EMBED + nw + cc;
#pragma unroll
                for (int nf = 0; nf < 8; ++nf)
                    *reinterpret_cast<float2*>(dst + nf * 8) =
                        make_float2(acc[mf][nf][half * 2],
                                    acc[mf][nf][half * 2 + 1]);
            }
        }
}

// ---------------------------------------------------------------------------
// Launch
// ---------------------------------------------------------------------------
extern "C" void kernel_launch(void* const* d_in, const int* in_sizes, int n_in,
                              void* d_out, int out_size) {
    const void*  node_ids  = d_in[0];
    const void*  node_tids = d_in[1];
    const void*  type_ids  = d_in[2];
    const float* feat0     = (const float*)d_in[3];
    const float* W0        = (const float*)d_in[4];
    const float* embed_tab = (const float*)d_in[5];
    float*       out       = (float*)d_out;

    cudaFuncSetAttribute(k_gemm_mma,
                         cudaFuncAttributeMaxDynamicSharedMemorySize, SMEM_TOTAL);

    k_prep<<<128, 256>>>(W0, (const int*)node_ids);
    k_compact_embed<<<512, 256>>>(node_ids, node_tids, type_ids, embed_tab, out);
    const int gemmBlocks = (NN + TM - 1) / TM;   // worst case: all type-0
    k_gemm_mma<<<gemmBlocks, GT, SMEM_TOTAL>>>(feat0, out);
}

// round 10
// speedup vs baseline: 1.1478x; 1.0003x over previous
#include <cuda_runtime.h>
#include <cuda_bf16.h>
#include <cstdint>

// ---------------------------------------------------------------------------
// Problem constants
// ---------------------------------------------------------------------------
#define NN     500000
#define D_IN   256
#define EMBED  128
#define TM     128        // rows per GEMM tile
#define KC     128        // K elems per A chunk (2 chunks)
#define GT     256        // GEMM block threads

// SMEM layout (bytes), all 16B-aligned.
// B: [n][k] bf16, full K=256, row stride 528B (512 + 16 pad -> stride%128B = 16,
//    i.e. 4 banks mod 32 -> ldmatrix conflict-free across 8-row groups).
// A: [r][k] bf16 per 128-K chunk, row stride 272B (256 + 16 pad), same property.
#define SB_STRIDE  528
#define SA_STRIDE  272
#define SM_B_HI    0
#define SM_B_LO    67584        // 128*528
#define SM_A_HI    135168
#define SM_A_LO    169984       // +128*272
#define SM_SROW    204800
#define SM_SFEAT   205312
#define SMEM_TOTAL 205824

// ---------------------------------------------------------------------------
// Device scratch (no cudaMalloc allowed)
// ---------------------------------------------------------------------------
__device__ int g_count;
__device__ int g_is64;
__device__ int g_rows[NN];
__device__ int g_feat[NN];
__device__ __align__(16) __nv_bfloat16 g_W0T_hi[EMBED * D_IN];  // [n][k]
__device__ __align__(16) __nv_bfloat16 g_W0T_lo[EMBED * D_IN];

// ---------------------------------------------------------------------------
// PTX helpers (base sm_103 ISA only: ldmatrix + mma.sync)
// ---------------------------------------------------------------------------
__device__ __forceinline__ uint32_t smem_u32(const void* p) {
    uint32_t a;
    asm("{ .reg .u64 t; cvta.to.shared.u64 t, %1; cvt.u32.u64 %0, t; }"
        : "=r"(a) : "l"(p));
    return a;
}
__device__ __forceinline__ void ldsm_x4(uint32_t* r, uint32_t addr) {
    asm volatile("ldmatrix.sync.aligned.m8n8.x4.shared.b16 {%0,%1,%2,%3}, [%4];"
                 : "=r"(r[0]), "=r"(r[1]), "=r"(r[2]), "=r"(r[3]) : "r"(addr));
}
__device__ __forceinline__ void mma_bf16(float* d, const uint32_t* a,
                                         const uint32_t* b) {
    asm volatile(
        "mma.sync.aligned.m16n8k16.row.col.f32.bf16.bf16.f32 "
        "{%0,%1,%2,%3}, {%4,%5,%6,%7}, {%8,%9}, {%0,%1,%2,%3};"
        : "+f"(d[0]), "+f"(d[1]), "+f"(d[2]), "+f"(d[3])
        : "r"(a[0]), "r"(a[1]), "r"(a[2]), "r"(a[3]), "r"(b[0]), "r"(b[1]));
}

// Dtype-agnostic index read
__device__ __forceinline__ int read_idx(const void* p, int i, int is64) {
    if (is64) return (int)((const long long*)p)[i];
    return ((const int*)p)[i];
}

// Split 8 floats into bf16 hi/lo and store as one uint4 each.
__device__ __forceinline__ void split8_store(char* smem, uint32_t off_hi,
                                             const float* f) {
    uint32_t hw[4], lw[4];
#pragma unroll
    for (int q = 0; q < 4; ++q) {
        const float a = f[2 * q], b = f[2 * q + 1];
        const __nv_bfloat16 ah = __float2bfloat16_rn(a);
        const __nv_bfloat16 bh = __float2bfloat16_rn(b);
        const __nv_bfloat16 al = __float2bfloat16_rn(a - __bfloat162float(ah));
        const __nv_bfloat16 bl = __float2bfloat16_rn(b - __bfloat162float(bh));
        hw[q] = (uint32_t)__bfloat16_as_ushort(ah) |
                ((uint32_t)__bfloat16_as_ushort(bh) << 16);
        lw[q] = (uint32_t)__bfloat16_as_ushort(al) |
                ((uint32_t)__bfloat16_as_ushort(bl) << 16);
    }
    *reinterpret_cast<uint4*>(smem + off_hi) = make_uint4(hw[0], hw[1], hw[2], hw[3]);
    *reinterpret_cast<uint4*>(smem + off_hi + (SM_A_LO - SM_A_HI)) =
        make_uint4(lw[0], lw[1], lw[2], lw[3]);
}

// Convert + store one 128xKC A chunk (thread t: row t>>1, K-half t&1 = 64 floats)
__device__ __forceinline__ void store_A_chunk(char* smem, int tid, const float4* v) {
    const int r = tid >> 1, h = tid & 1;
#pragma unroll
    for (int j = 0; j < 8; ++j) {
        const float f[8] = {v[2*j].x,   v[2*j].y,   v[2*j].z,   v[2*j].w,
                            v[2*j+1].x, v[2*j+1].y, v[2*j+1].z, v[2*j+1].w};
        split8_store(smem, (uint32_t)(SM_A_HI + r * SA_STRIDE + h * 128 + j * 16), f);
    }
}

// ---------------------------------------------------------------------------
// Kernel 0: reset counter + dtype detect + W0^T hi/lo prep (fused)
// ---------------------------------------------------------------------------
__global__ void k_prep(const float* __restrict__ W0, const int* node_ids_as_i32) {
    if (blockIdx.x == 0 && threadIdx.x < 32) {
        bool odd_zero = true;
        for (int j = threadIdx.x; j < 64; j += 32)
            if (node_ids_as_i32[2 * j + 1] != 0) odd_zero = false;
        const unsigned b = __ballot_sync(0xffffffffu, odd_zero);
        if (threadIdx.x == 0) {
            g_is64  = (b == 0xffffffffu) ? 1 : 0;
            g_count = 0;
        }
    }
    const int idx = blockIdx.x * blockDim.x + threadIdx.x;  // 0..32767
    const int n = idx >> 8, k = idx & 255;
    const float x = W0[k * EMBED + n];
    const __nv_bfloat16 hi = __float2bfloat16_rn(x);
    const __nv_bfloat16 lo = __float2bfloat16_rn(x - __bfloat162float(hi));
    g_W0T_hi[n * D_IN + k] = hi;
    g_W0T_lo[n * D_IN + k] = lo;
}

// ---------------------------------------------------------------------------
// Kernel 1: warp-aggregated compaction of type-0 nodes + fused embedding copy
// ---------------------------------------------------------------------------
__global__ void k_compact_embed(const void* __restrict__ node_ids,
                                const void* __restrict__ node_tids,
                                const void* __restrict__ type_ids,
                                const float* __restrict__ embed_table,
                                float* __restrict__ out) {
    const int is64    = g_is64;
    const int lane    = threadIdx.x & 31;
    const int warpId  = (blockIdx.x * blockDim.x + threadIdx.x) >> 5;
    const int nWarps  = (gridDim.x * blockDim.x) >> 5;
    const int nChunks = (NN + 31) >> 5;

    for (int chunk = warpId; chunk < nChunks; chunk += nWarps) {
        const int base = chunk << 5;
        const int i    = base + lane;
        const bool valid = (i < NN);

        int tid_i = -1, my_nid = 0, my_feat = 0;
        if (valid) {
            tid_i   = read_idx(node_tids, i, is64);
            my_nid  = read_idx(node_ids,  i, is64);
            my_feat = read_idx(type_ids,  i, is64);
        }

        const unsigned mask0 = __ballot_sync(0xffffffffu, valid && tid_i == 0);
        const int cnt = __popc(mask0);
        int posBase = 0;
        if (lane == 0 && cnt > 0) posBase = atomicAdd(&g_count, cnt);
        posBase = __shfl_sync(0xffffffffu, posBase, 0);
        if (valid && tid_i == 0) {
            const int rank = __popc(mask0 & ((1u << lane) - 1u));
            g_rows[posBase + rank] = i;
            g_feat[posBase + rank] = my_feat;
        }

        unsigned mask1 = __ballot_sync(0xffffffffu, valid && tid_i == 1);
        while (mask1) {
            const int j = __ffs(mask1) - 1;
            mask1 &= mask1 - 1;
            const int nid = __shfl_sync(0xffffffffu, my_nid, j);
            const float4* src = reinterpret_cast<const float4*>(
                embed_table + (size_t)nid * EMBED);
            float4* dst = reinterpret_cast<float4*>(
                out + (size_t)(base + j) * EMBED);
            dst[lane] = src[lane];
        }
    }
}

// ---------------------------------------------------------------------------
// Kernel 2: HMMA split-bf16 gathered GEMM.
// D[128,128] = sum over K of (Ahi+Alo)(Bhi+Blo), dropping lo*lo (~4e-6 rel).
// 8 warps; warp w: rows (w&3)*32..+31, cols (w>>2)*64..+63.
// ---------------------------------------------------------------------------
__global__ void __launch_bounds__(GT)
k_gemm_mma(const float* __restrict__ feat0, float* __restrict__ out) {
    extern __shared__ __align__(16) char smem[];

    const int count = g_count;
    const int m0 = blockIdx.x * TM;
    if (m0 >= count) return;
    const int rows = min(TM, count - m0);

    const int tid  = threadIdx.x;
    const int w    = tid >> 5;
    const int lane = tid & 31;
    const int mw   = (w & 3) * 32;
    const int nw   = (w >> 2) * 64;
    const uint32_t sb = smem_u32(smem);

    int* srow  = reinterpret_cast<int*>(smem + SM_SROW);
    int* sfeat = reinterpret_cast<int*>(smem + SM_SFEAT);
    if (tid < TM) {
        const bool v = tid < rows;
        srow[tid]  = v ? g_rows[m0 + tid] : 0;
        sfeat[tid] = v ? g_feat[m0 + tid] : g_feat[m0];
    }

    // --- stage B (W0^T hi/lo, full K) into padded SMEM ---
    {
        const int n = tid >> 1, h = tid & 1;
        const uint4* srcH = reinterpret_cast<const uint4*>(g_W0T_hi + n * D_IN + h * 128);
        const uint4* srcL = reinterpret_cast<const uint4*>(g_W0T_lo + n * D_IN + h * 128);
        char* dstH = smem + SM_B_HI + n * SB_STRIDE + h * 256;
        char* dstL = smem + SM_B_LO + n * SB_STRIDE + h * 256;
#pragma unroll
        for (int j = 0; j < 16; ++j) {
            *reinterpret_cast<uint4*>(dstH + j * 16) = srcH[j];
            *reinterpret_cast<uint4*>(dstL + j * 16) = srcL[j];
        }
    }
    __syncthreads();

    // --- gather + convert A chunk 0 ---
    const int ar = tid >> 1, ah = tid & 1;
    const float4* arow = reinterpret_cast<const float4*>(
        feat0 + (size_t)sfeat[ar] * D_IN) + ah * 16;

    float4 v[16];
#pragma unroll
    for (int j = 0; j < 16; ++j) v[j] = arow[j];
    store_A_chunk(smem, tid, v);
    __syncthreads();

    // prefetch chunk 1 (overlaps chunk-0 MMA; 1 block/SM -> regs are free)
#pragma unroll
    for (int j = 0; j < 16; ++j) v[j] = arow[32 + j];

    float acc[2][8][4];
#pragma unroll
    for (int mf = 0; mf < 2; ++mf)
#pragma unroll
        for (int nf = 0; nf < 8; ++nf)
#pragma unroll
            for (int q = 0; q < 4; ++q) acc[mf][nf][q] = 0.0f;

    // ldmatrix lane address components (constant across ksteps)
    const uint32_t a_row  = (uint32_t)(mw + (lane & 15));
    const uint32_t a_coff = (uint32_t)((lane >> 4) * 16);
    const uint32_t b_row  = (uint32_t)(nw + (lane >> 4) * 8 + (lane & 7));
    const uint32_t b_coff = (uint32_t)(((lane >> 3) & 1) * 16);

    for (int chunk = 0; chunk < 2; ++chunk) {
#pragma unroll
        for (int kk = 0; kk < KC / 16; ++kk) {
            const uint32_t kbA = (uint32_t)(kk * 32) + a_coff;
            const uint32_t kbB = (uint32_t)(chunk * 256 + kk * 32) + b_coff;

            uint32_t ahi[2][4], alo[2][4];
#pragma unroll
            for (int mf = 0; mf < 2; ++mf) {
                const uint32_t addr =
                    sb + SM_A_HI + (a_row + mf * 16) * SA_STRIDE + kbA;
                ldsm_x4(ahi[mf], addr);
                ldsm_x4(alo[mf], addr + (SM_A_LO - SM_A_HI));
            }
            uint32_t bhi[8][2], blo[8][2];
#pragma unroll
            for (int np = 0; np < 4; ++np) {
                const uint32_t addr =
                    sb + SM_B_HI + (b_row + np * 16) * SB_STRIDE + kbB;
                uint32_t t[4];
                ldsm_x4(t, addr);
                bhi[np*2][0] = t[0]; bhi[np*2][1] = t[1];
                bhi[np*2+1][0] = t[2]; bhi[np*2+1][1] = t[3];
                ldsm_x4(t, addr + (SM_B_LO - SM_B_HI));
                blo[np*2][0] = t[0]; blo[np*2][1] = t[1];
                blo[np*2+1][0] = t[2]; blo[np*2+1][1] = t[3];
            }
#pragma unroll
            for (int mf = 0; mf < 2; ++mf)
#pragma unroll
                for (int nf = 0; nf < 8; ++nf) {
                    mma_bf16(acc[mf][nf], ahi[mf], bhi[nf]);
                    mma_bf16(acc[mf][nf], ahi[mf], blo[nf]);
                    mma_bf16(acc[mf][nf], alo[mf], bhi[nf]);
                }
        }
        if (chunk == 0) {
            __syncthreads();              // all ldmatrix of chunk 0 done
            store_A_chunk(smem, tid, v);  // overwrite A with chunk 1
            __syncthreads();
        }
    }

    // --- epilogue: scatter accumulators to out ---
    const int cr0 = lane >> 2;            // fragment row 0..7
    const int cc  = (lane & 3) * 2;       // fragment col (2 floats)
#pragma unroll
    for (int mf = 0; mf < 2; ++mf)
#pragma unroll
        for (int half = 0; half < 2; ++half) {
            const int rloc = mw + mf * 16 + cr0 + half * 8;
            if (rloc < rows) {
                float* dst = out + (size_t)srow[rloc] * EMBED + nw + cc;
#pragma unroll
                for (int nf = 0; nf < 8; ++nf)
                    *reinterpret_cast<float2*>(dst + nf * 8) =
                        make_float2(acc[mf][nf][half * 2],
                                    acc[mf][nf][half * 2 + 1]);
            }
        }
}

// ---------------------------------------------------------------------------
// Launch
// ---------------------------------------------------------------------------
extern "C" void kernel_launch(void* const* d_in, const int* in_sizes, int n_in,
                              void* d_out, int out_size) {
    const void*  node_ids  = d_in[0];
    const void*  node_tids = d_in[1];
    const void*  type_ids  = d_in[2];
    const float* feat0     = (const float*)d_in[3];
    const float* W0        = (const float*)d_in[4];
    const float* embed_tab = (const float*)d_in[5];
    float*       out       = (float*)d_out;

    cudaFuncSetAttribute(k_gemm_mma,
                         cudaFuncAttributeMaxDynamicSharedMemorySize, SMEM_TOTAL);

    k_prep<<<128, 256>>>(W0, (const int*)node_ids);
    k_compact_embed<<<512, 256>>>(node_ids, node_tids, type_ids, embed_tab, out);
    const int gemmBlocks = (NN + TM - 1) / TM;   // worst case: all type-0
    k_gemm_mma<<<gemmBlocks, GT, SMEM_TOTAL>>>(feat0, out);
}

// round 11
// speedup vs baseline: 1.1519x; 1.0035x over previous
#include <cuda_runtime.h>
#include <cuda_bf16.h>
#include <cstdint>

// ---------------------------------------------------------------------------
// Problem constants
// ---------------------------------------------------------------------------
#define NN     500000
#define D_IN   256
#define EMBED  128
#define TM     128        // rows per GEMM tile
#define KC     128        // K elems per A chunk (2 chunks)
#define GT     256        // GEMM block threads

// SMEM layout (bytes), all 16B-aligned.
// B: [n][k] bf16, full K=256, row stride 528B (512 + 16 pad -> stride%128B = 16,
//    i.e. 4 banks mod 32 -> ldmatrix conflict-free across 8-row groups).
// A: [r][k] bf16 per 128-K chunk, row stride 272B (256 + 16 pad), same property.
#define SB_STRIDE  528
#define SA_STRIDE  272
#define SM_B_HI    0
#define SM_B_LO    67584        // 128*528
#define SM_A_HI    135168
#define SM_A_LO    169984       // +128*272
#define SM_SROW    204800
#define SM_SFEAT   205312
#define SMEM_TOTAL 205824

// ---------------------------------------------------------------------------
// Device scratch (no cudaMalloc allowed)
// ---------------------------------------------------------------------------
__device__ int g_count;
__device__ int g_is64;
__device__ int g_rows[NN];
__device__ int g_feat[NN];
__device__ __align__(16) __nv_bfloat16 g_W0T_hi[EMBED * D_IN];  // [n][k]
__device__ __align__(16) __nv_bfloat16 g_W0T_lo[EMBED * D_IN];

// ---------------------------------------------------------------------------
// PTX helpers (base sm_103 ISA only: ldmatrix + mma.sync)
// ---------------------------------------------------------------------------
__device__ __forceinline__ uint32_t smem_u32(const void* p) {
    uint32_t a;
    asm("{ .reg .u64 t; cvta.to.shared.u64 t, %1; cvt.u32.u64 %0, t; }"
        : "=r"(a) : "l"(p));
    return a;
}
__device__ __forceinline__ void ldsm_x4(uint32_t* r, uint32_t addr) {
    asm volatile("ldmatrix.sync.aligned.m8n8.x4.shared.b16 {%0,%1,%2,%3}, [%4];"
                 : "=r"(r[0]), "=r"(r[1]), "=r"(r[2]), "=r"(r[3]) : "r"(addr));
}
__device__ __forceinline__ void mma_bf16(float* d, const uint32_t* a,
                                         const uint32_t* b) {
    asm volatile(
        "mma.sync.aligned.m16n8k16.row.col.f32.bf16.bf16.f32 "
        "{%0,%1,%2,%3}, {%4,%5,%6,%7}, {%8,%9}, {%0,%1,%2,%3};"
        : "+f"(d[0]), "+f"(d[1]), "+f"(d[2]), "+f"(d[3])
        : "r"(a[0]), "r"(a[1]), "r"(a[2]), "r"(a[3]), "r"(b[0]), "r"(b[1]));
}

// Dtype-agnostic index read
__device__ __forceinline__ int read_idx(const void* p, int i, int is64) {
    if (is64) return (int)((const long long*)p)[i];
    return ((const int*)p)[i];
}

// Split 8 floats into bf16 hi/lo and store as one uint4 each.
__device__ __forceinline__ void split8_store(char* smem, uint32_t off_hi,
                                             const float* f) {
    uint32_t hw[4], lw[4];
#pragma unroll
    for (int q = 0; q < 4; ++q) {
        const float a = f[2 * q], b = f[2 * q + 1];
        const __nv_bfloat16 ah = __float2bfloat16_rn(a);
        const __nv_bfloat16 bh = __float2bfloat16_rn(b);
        const __nv_bfloat16 al = __float2bfloat16_rn(a - __bfloat162float(ah));
        const __nv_bfloat16 bl = __float2bfloat16_rn(b - __bfloat162float(bh));
        hw[q] = (uint32_t)__bfloat16_as_ushort(ah) |
                ((uint32_t)__bfloat16_as_ushort(bh) << 16);
        lw[q] = (uint32_t)__bfloat16_as_ushort(al) |
                ((uint32_t)__bfloat16_as_ushort(bl) << 16);
    }
    *reinterpret_cast<uint4*>(smem + off_hi) = make_uint4(hw[0], hw[1], hw[2], hw[3]);
    *reinterpret_cast<uint4*>(smem + off_hi + (SM_A_LO - SM_A_HI)) =
        make_uint4(lw[0], lw[1], lw[2], lw[3]);
}

// Convert + store one 128xKC A chunk (thread t: row t>>1, K-half t&1 = 64 floats)
__device__ __forceinline__ void store_A_chunk(char* smem, int tid, const float4* v) {
    const int r = tid >> 1, h = tid & 1;
#pragma unroll
    for (int j = 0; j < 8; ++j) {
        const float f[8] = {v[2*j].x,   v[2*j].y,   v[2*j].z,   v[2*j].w,
                            v[2*j+1].x, v[2*j+1].y, v[2*j+1].z, v[2*j+1].w};
        split8_store(smem, (uint32_t)(SM_A_HI + r * SA_STRIDE + h * 128 + j * 16), f);
    }
}

// ---------------------------------------------------------------------------
// Kernel 0: reset counter + dtype detect + W0^T hi/lo prep (fused)
// ---------------------------------------------------------------------------
__global__ void k_prep(const float* __restrict__ W0, const int* node_ids_as_i32) {
    if (blockIdx.x == 0 && threadIdx.x < 32) {
        bool odd_zero = true;
        for (int j = threadIdx.x; j < 64; j += 32)
            if (node_ids_as_i32[2 * j + 1] != 0) odd_zero = false;
        const unsigned b = __ballot_sync(0xffffffffu, odd_zero);
        if (threadIdx.x == 0) {
            g_is64  = (b == 0xffffffffu) ? 1 : 0;
            g_count = 0;
        }
    }
    const int idx = blockIdx.x * blockDim.x + threadIdx.x;  // 0..32767
    const int n = idx >> 8, k = idx & 255;
    const float x = W0[k * EMBED + n];
    const __nv_bfloat16 hi = __float2bfloat16_rn(x);
    const __nv_bfloat16 lo = __float2bfloat16_rn(x - __bfloat162float(hi));
    g_W0T_hi[n * D_IN + k] = hi;
    g_W0T_lo[n * D_IN + k] = lo;
}

// ---------------------------------------------------------------------------
// Kernel 1: warp-aggregated compaction of type-0 nodes + fused embedding copy
// ---------------------------------------------------------------------------
__global__ void k_compact_embed(const void* __restrict__ node_ids,
                                const void* __restrict__ node_tids,
                                const void* __restrict__ type_ids,
                                const float* __restrict__ embed_table,
                                float* __restrict__ out) {
    const int is64    = g_is64;
    const int lane    = threadIdx.x & 31;
    const int warpId  = (blockIdx.x * blockDim.x + threadIdx.x) >> 5;
    const int nWarps  = (gridDim.x * blockDim.x) >> 5;
    const int nChunks = (NN + 31) >> 5;

    for (int chunk = warpId; chunk < nChunks; chunk += nWarps) {
        const int base = chunk << 5;
        const int i    = base + lane;
        const bool valid = (i < NN);

        int tid_i = -1, my_nid = 0, my_feat = 0;
        if (valid) {
            tid_i   = read_idx(node_tids, i, is64);
            my_nid  = read_idx(node_ids,  i, is64);
            my_feat = read_idx(type_ids,  i, is64);
        }

        const unsigned mask0 = __ballot_sync(0xffffffffu, valid && tid_i == 0);
        const int cnt = __popc(mask0);
        int posBase = 0;
        if (lane == 0 && cnt > 0) posBase = atomicAdd(&g_count, cnt);
        posBase = __shfl_sync(0xffffffffu, posBase, 0);
        if (valid && tid_i == 0) {
            const int rank = __popc(mask0 & ((1u << lane) - 1u));
            g_rows[posBase + rank] = i;
            g_feat[posBase + rank] = my_feat;
        }

        unsigned mask1 = __ballot_sync(0xffffffffu, valid && tid_i == 1);
        while (mask1) {
            const int j = __ffs(mask1) - 1;
            mask1 &= mask1 - 1;
            const int nid = __shfl_sync(0xffffffffu, my_nid, j);
            const float4* src = reinterpret_cast<const float4*>(
                embed_table + (size_t)nid * EMBED);
            float4* dst = reinterpret_cast<float4*>(
                out + (size_t)(base + j) * EMBED);
            dst[lane] = src[lane];
        }
    }
}

// ---------------------------------------------------------------------------
// Kernel 2: HMMA split-bf16 gathered GEMM.
// D[128,128] = sum over K of (Ahi+Alo)(Bhi+Blo), dropping lo*lo (~4e-6 rel).
// 8 warps; warp w: rows (w&3)*32..+31, cols (w>>2)*64..+63.
// ---------------------------------------------------------------------------
__global__ void __launch_bounds__(GT)
k_gemm_mma(const float* __restrict__ feat0, float* __restrict__ out) {
    extern __shared__ __align__(16) char smem[];

    const int count = g_count;
    const int m0 = blockIdx.x * TM;
    if (m0 >= count) return;
    const int rows = min(TM, count - m0);

    const int tid  = threadIdx.x;
    const int w    = tid >> 5;
    const int lane = tid & 31;
    const int mw   = (w & 3) * 32;
    const int nw   = (w >> 2) * 64;
    const uint32_t sb = smem_u32(smem);

    int* srow  = reinterpret_cast<int*>(smem + SM_SROW);
    int* sfeat = reinterpret_cast<int*>(smem + SM_SFEAT);
    if (tid < TM) {
        const bool v = tid < rows;
        srow[tid]  = v ? g_rows[m0 + tid] : 0;
        sfeat[tid] = v ? g_feat[m0 + tid] : g_feat[m0];
    }

    // --- stage B (W0^T hi/lo, full K) into padded SMEM ---
    {
        const int n = tid >> 1, h = tid & 1;
        const uint4* srcH = reinterpret_cast<const uint4*>(g_W0T_hi + n * D_IN + h * 128);
        const uint4* srcL = reinterpret_cast<const uint4*>(g_W0T_lo + n * D_IN + h * 128);
        char* dstH = smem + SM_B_HI + n * SB_STRIDE + h * 256;
        char* dstL = smem + SM_B_LO + n * SB_STRIDE + h * 256;
#pragma unroll
        for (int j = 0; j < 16; ++j) {
            *reinterpret_cast<uint4*>(dstH + j * 16) = srcH[j];
            *reinterpret_cast<uint4*>(dstL + j * 16) = srcL[j];
        }
    }
    __syncthreads();

    // --- gather + convert A chunk 0 ---
    const int ar = tid >> 1, ah = tid & 1;
    const float4* arow = reinterpret_cast<const float4*>(
        feat0 + (size_t)sfeat[ar] * D_IN) + ah * 16;

    float4 v[16];
#pragma unroll
    for (int j = 0; j < 16; ++j) v[j] = arow[j];
    store_A_chunk(smem, tid, v);
    __syncthreads();

    // prefetch chunk 1 (overlaps chunk-0 MMA; 1 block/SM -> regs are free)
#pragma unroll
    for (int j = 0; j < 16; ++j) v[j] = arow[32 + j];

    float acc[2][8][4];
#pragma unroll
    for (int mf = 0; mf < 2; ++mf)
#pragma unroll
        for (int nf = 0; nf < 8; ++nf)
#pragma unroll
            for (int q = 0; q < 4; ++q) acc[mf][nf][q] = 0.0f;

    // ldmatrix lane address components (constant across ksteps)
    const uint32_t a_row  = (uint32_t)(mw + (lane & 15));
    const uint32_t a_coff = (uint32_t)((lane >> 4) * 16);
    const uint32_t b_row  = (uint32_t)(nw + (lane >> 4) * 8 + (lane & 7));
    const uint32_t b_coff = (uint32_t)(((lane >> 3) & 1) * 16);

    for (int chunk = 0; chunk < 2; ++chunk) {
#pragma unroll
        for (int kk = 0; kk < KC / 16; ++kk) {
            const uint32_t kbA = (uint32_t)(kk * 32) + a_coff;
            const uint32_t kbB = (uint32_t)(chunk * 256 + kk * 32) + b_coff;

            uint32_t ahi[2][4], alo[2][4];
#pragma unroll
            for (int mf = 0; mf < 2; ++mf) {
                const uint32_t addr =
                    sb + SM_A_HI + (a_row + mf * 16) * SA_STRIDE + kbA;
                ldsm_x4(ahi[mf], addr);
                ldsm_x4(alo[mf], addr + (SM_A_LO - SM_A_HI));
            }
            uint32_t bhi[8][2], blo[8][2];
#pragma unroll
            for (int np = 0; np < 4; ++np) {
                const uint32_t addr =
                    sb + SM_B_HI + (b_row + np * 16) * SB_STRIDE + kbB;
                uint32_t t[4];
                ldsm_x4(t, addr);
                bhi[np*2][0] = t[0]; bhi[np*2][1] = t[1];
                bhi[np*2+1][0] = t[2]; bhi[np*2+1][1] = t[3];
                ldsm_x4(t, addr + (SM_B_LO - SM_B_HI));
                blo[np*2][0] = t[0]; blo[np*2][1] = t[1];
                blo[np*2+1][0] = t[2]; blo[np*2+1][1] = t[3];
            }
#pragma unroll
            for (int mf = 0; mf < 2; ++mf)
#pragma unroll
                for (int nf = 0; nf < 8; ++nf) {
                    mma_bf16(acc[mf][nf], ahi[mf], bhi[nf]);
                    mma_bf16(acc[mf][nf], ahi[mf], blo[nf]);
                    mma_bf16(acc[mf][nf], alo[mf], bhi[nf]);
                }
        }
        if (chunk == 0) {
            __syncthreads();              // all ldmatrix of chunk 0 done
            store_A_chunk(smem, tid, v);  // overwrite A with chunk 1
            __syncthreads();
        }
    }

    // --- epilogue: scatter accumulators to out ---
    const int cr0 = lane >> 2;            // fragment row 0..7
    const int cc  = (lane & 3) * 2;       // fragment col (2 floats)
#pragma unroll
    for (int mf = 0; mf < 2; ++mf)
#pragma unroll
        for (int half = 0; half < 2; ++half) {
            const int rloc = mw + mf * 16 + cr0 + half * 8;
            if (rloc < rows) {
                float* dst = out + (size_t)srow[rloc] * EMBED + nw + cc;
#pragma unroll
                for (int nf = 0; nf < 8; ++nf)
                    *reinterpret_cast<float2*>(dst + nf * 8) =
                        make_float2(acc[mf][nf][half * 2],
                                    acc[mf][nf][half * 2 + 1]);
            }
        }
}

// ---------------------------------------------------------------------------
// Launch
// ---------------------------------------------------------------------------
extern "C" void kernel_launch(void* const* d_in, const int* in_sizes, int n_in,
                              void* d_out, int out_size) {
    const void*  node_ids  = d_in[0];
    const void*  node_tids = d_in[1];
    const void*  type_ids  = d_in[2];
    const float* feat0     = (const float*)d_in[3];
    const float* W0        = (const float*)d_in[4];
    const float* embed_tab = (const float*)d_in[5];
    float*       out       = (float*)d_out;

    cudaFuncSetAttribute(k_gemm_mma,
                         cudaFuncAttributeMaxDynamicSharedMemorySize, SMEM_TOTAL);

    k_prep<<<128, 256>>>(W0, (const int*)node_ids);
    k_compact_embed<<<512, 256>>>(node_ids, node_tids, type_ids, embed_tab, out);
    const int gemmBlocks = (NN + TM - 1) / TM;   // worst case: all type-0
    k_gemm_mma<<<gemmBlocks, GT, SMEM_TOTAL>>>(feat0, out);
}